// round 13
// baseline (speedup 1.0000x reference)
#include <cuda_runtime.h>
#include <cuda_bf16.h>

#define NN 50000
#define EE 800000
#define F_INN 256
#define F_EDGE 64
#define NH 4
#define ND 64
#define HD 256
#define NEG_SLOPE 0.2f

// ---------------- scratch (static device globals; no allocation) ----------------
// invariant: g_cnt / g_cur are all-zero before every kernel_launch call
// (zero-init at load; k_agg restores them at the end of each run)
__device__ __nv_bfloat162 g_featb[NN * 128]; // h @ W_fc^T in bf16 pairs
__device__ float g_res[NN * HD];             // h @ W_res^T
__device__ float g_el[NN * NH];
__device__ float g_er[NN * NH];
__device__ float g_V[F_EDGE * NH];           // collapsed W_edge x attn_e, layout [j][h]
__device__ int   g_cnt[NN];                  // in-degree
__device__ int   g_off[NN];                  // CSR offsets (exclusive scan of cnt)
__device__ int   g_cur[NN];                  // scatter cursors
__device__ int   g_esrc[EE];                 // CSR: src node per slot
__device__ float g_eex[EE * NH];             // CSR: exp(e) per slot, 4 heads

// ---------------- helpers ----------------
__device__ __forceinline__ unsigned f2tf32(float f) {
    unsigned u;
    asm("cvt.rna.tf32.f32 %0, %1;" : "=r"(u) : "f"(f));
    return u;
}

__device__ __forceinline__ void mma_tf32(float& c0, float& c1, float& c2, float& c3,
                                         unsigned a0, unsigned a1, unsigned a2, unsigned a3,
                                         unsigned b0, unsigned b1) {
    asm volatile("mma.sync.aligned.m16n8k8.row.col.f32.tf32.tf32.f32 "
                 "{%0,%1,%2,%3}, {%4,%5,%6,%7}, {%8,%9}, {%0,%1,%2,%3};"
                 : "+f"(c0), "+f"(c1), "+f"(c2), "+f"(c3)
                 : "r"(a0), "r"(a1), "r"(a2), "r"(a3), "r"(b0), "r"(b1));
}

__device__ __forceinline__ void cp16(float* smem, const float* gmem) {
    unsigned s = (unsigned)__cvta_generic_to_shared(smem);
    asm volatile("cp.async.cg.shared.global [%0], [%1], 16;" :: "r"(s), "l"(gmem));
}

// ---------------- K1: prep V (block 0) + degree count ----------------
__global__ void k_pre(const float* __restrict__ W_edge, const float* __restrict__ attn_e,
                      const int* __restrict__ dst) {
    if (blockIdx.x == 0 && threadIdx.x < 256) {
        int j = threadIdx.x & 63, h = threadIdx.x >> 6;
        float s = 0.0f;
        #pragma unroll 8
        for (int d = 0; d < 64; d++)
            s += W_edge[(h * 64 + d) * 64 + j] * attn_e[h * 64 + d];
        g_V[j * 4 + h] = s;
    }
    int e = blockIdx.x * blockDim.x + threadIdx.x;
    if (e < EE) atomicAdd(&g_cnt[dst[e]], 1);
}

// ---------------- K2: tf32 GEMM (cp.async, cvt.rna) + fused el/er epilogue ----
#define GBM 128
#define GBN 128
#define GBK 16
#define KT  (F_INN / GBK)   // 16
#define SPAD 20             // words per row; conflict-free frag loads

__global__ __launch_bounds__(256) void k_gemm_attn(const float* __restrict__ A,
                                                   const float* __restrict__ Wfc,
                                                   const float* __restrict__ Wres,
                                                   const float* __restrict__ attn_l,
                                                   const float* __restrict__ attn_r) {
    __shared__ float As[2][GBM * SPAD];
    __shared__ float Bs[2][GBN * SPAD];
    __shared__ float sdotL[512];
    __shared__ float sdotR[512];

    const int colbase = blockIdx.x * GBN;    // 0,128,256,384
    const int rowbase = blockIdx.y * GBM;
    const bool isfeat = (colbase < 256);
    const float* Bsrc = isfeat ? (Wfc + colbase * F_INN)
                               : (Wres + (colbase - 256) * F_INN);
    const int ccol0 = isfeat ? colbase : colbase - 256;

    const int tid  = threadIdx.x;
    const int w    = tid >> 5;
    const int lane = tid & 31;
    const int grp  = lane >> 2;     // 0..7
    const int tg   = lane & 3;      // 0..3
    const int wm   = w & 1;
    const int wn   = w >> 1;

    const int lr  = tid >> 2;          // 0..63 (+64 on second pass)
    const int lc4 = (tid & 3) * 4;     // 0,4,8,12

    float acc[4][4][4];
    #pragma unroll
    for (int mt = 0; mt < 4; mt++)
        #pragma unroll
        for (int nt = 0; nt < 4; nt++)
            #pragma unroll
            for (int r = 0; r < 4; r++) acc[mt][nt][r] = 0.0f;

    auto issue = [&](int kt, int buf) {
        int kk = kt * GBK;
        #pragma unroll
        for (int i = 0; i < 2; i++) {
            int r = lr + i * 64;
            int gr = rowbase + r;
            if (gr >= NN) gr = NN - 1;   // clamp; garbage rows never stored
            cp16(&As[buf][r * SPAD + lc4], &A[gr * F_INN + kk + lc4]);
            cp16(&Bs[buf][r * SPAD + lc4], &Bsrc[r * F_INN + kk + lc4]);
        }
    };

    issue(0, 0);
    asm volatile("cp.async.commit_group;");

    for (int kt = 0; kt < KT; kt++) {
        int buf = kt & 1;
        if (kt + 1 < KT) {
            issue(kt + 1, (kt + 1) & 1);
            asm volatile("cp.async.commit_group;");
            asm volatile("cp.async.wait_group 1;");
        } else {
            asm volatile("cp.async.wait_group 0;");
        }
        __syncthreads();

        #pragma unroll
        for (int ks = 0; ks < 2; ks++) {
            const int kof = ks * 8 + tg;
            unsigned af[4][4];
            #pragma unroll
            for (int mt = 0; mt < 4; mt++) {
                int r0 = wm * 64 + mt * 16 + grp;
                af[mt][0] = f2tf32(As[buf][r0 * SPAD + kof]);
                af[mt][1] = f2tf32(As[buf][(r0 + 8) * SPAD + kof]);
                af[mt][2] = f2tf32(As[buf][r0 * SPAD + kof + 4]);
                af[mt][3] = f2tf32(As[buf][(r0 + 8) * SPAD + kof + 4]);
            }
            unsigned bf[4][2];
            #pragma unroll
            for (int nt = 0; nt < 4; nt++) {
                int c0 = wn * 32 + nt * 8 + grp;
                bf[nt][0] = f2tf32(Bs[buf][c0 * SPAD + kof]);
                bf[nt][1] = f2tf32(Bs[buf][c0 * SPAD + kof + 4]);
            }
            #pragma unroll
            for (int mt = 0; mt < 4; mt++)
                #pragma unroll
                for (int nt = 0; nt < 4; nt++)
                    mma_tf32(acc[mt][nt][0], acc[mt][nt][1], acc[mt][nt][2], acc[mt][nt][3],
                             af[mt][0], af[mt][1], af[mt][2], af[mt][3],
                             bf[nt][0], bf[nt][1]);
        }
        __syncthreads();
    }

    // ---- store C ----
    #pragma unroll
    for (int mt = 0; mt < 4; mt++) {
        int row0 = rowbase + wm * 64 + mt * 16 + grp;
        int row1 = row0 + 8;
        #pragma unroll
        for (int nt = 0; nt < 4; nt++) {
            int col = ccol0 + wn * 32 + nt * 8 + 2 * tg;
            if (isfeat) {
                if (row0 < NN)
                    g_featb[row0 * 128 + (col >> 1)] =
                        __floats2bfloat162_rn(acc[mt][nt][0], acc[mt][nt][1]);
                if (row1 < NN)
                    g_featb[row1 * 128 + (col >> 1)] =
                        __floats2bfloat162_rn(acc[mt][nt][2], acc[mt][nt][3]);
            } else {
                if (row0 < NN)
                    *(float2*)&g_res[row0 * HD + col] = make_float2(acc[mt][nt][0], acc[mt][nt][1]);
                if (row1 < NN)
                    *(float2*)&g_res[row1 * HD + col] = make_float2(acc[mt][nt][2], acc[mt][nt][3]);
            }
        }
    }

    // ---- fused attention dots (feat blocks only) ----
    if (isfeat) {
        float al[4][2], ar[4][2];
        #pragma unroll
        for (int nt = 0; nt < 4; nt++) {
            int gc = colbase + wn * 32 + nt * 8 + 2 * tg;
            al[nt][0] = attn_l[gc]; al[nt][1] = attn_l[gc + 1];
            ar[nt][0] = attn_r[gc]; ar[nt][1] = attn_r[gc + 1];
        }
        #pragma unroll
        for (int mt = 0; mt < 4; mt++) {
            float pl0 = 0.f, pl1 = 0.f, pr0 = 0.f, pr1 = 0.f;
            #pragma unroll
            for (int nt = 0; nt < 4; nt++) {
                pl0 += acc[mt][nt][0] * al[nt][0] + acc[mt][nt][1] * al[nt][1];
                pl1 += acc[mt][nt][2] * al[nt][0] + acc[mt][nt][3] * al[nt][1];
                pr0 += acc[mt][nt][0] * ar[nt][0] + acc[mt][nt][1] * ar[nt][1];
                pr1 += acc[mt][nt][2] * ar[nt][0] + acc[mt][nt][3] * ar[nt][1];
            }
            // reduce over tg (4 consecutive lanes)
            #pragma unroll
            for (int o = 2; o; o >>= 1) {
                pl0 += __shfl_down_sync(0xffffffffu, pl0, o, 4);
                pl1 += __shfl_down_sync(0xffffffffu, pl1, o, 4);
                pr0 += __shfl_down_sync(0xffffffffu, pr0, o, 4);
                pr1 += __shfl_down_sync(0xffffffffu, pr1, o, 4);
            }
            if (tg == 0) {
                int hb = wn >> 1, wlo = wn & 1;
                int base = ((((wm * 2 + hb) * 2 + wlo) * 4 + mt) * 8 + grp) * 2;
                sdotL[base + 0] = pl0; sdotL[base + 1] = pl1;
                sdotR[base + 0] = pr0; sdotR[base + 1] = pr1;
            }
        }
        __syncthreads();
        // 256 threads: one (row, head) each
        int t = tid;
        int rhalf = t & 1, grp2 = (t >> 1) & 7, mt2 = (t >> 4) & 3;
        int hb2 = (t >> 6) & 1, wm2 = (t >> 7) & 1;
        int i0 = ((((wm2 * 2 + hb2) * 2 + 0) * 4 + mt2) * 8 + grp2) * 2 + rhalf;
        int i1 = ((((wm2 * 2 + hb2) * 2 + 1) * 4 + mt2) * 8 + grp2) * 2 + rhalf;
        int row = rowbase + wm2 * 64 + mt2 * 16 + rhalf * 8 + grp2;
        int headg = (colbase >> 6) + hb2;
        if (row < NN) {
            g_el[row * 4 + headg] = sdotL[i0] + sdotL[i1];
            g_er[row * 4 + headg] = sdotR[i0] + sdotR[i1];
        }
    }
}

// ---------------- K3: single-block scan of g_cnt -> g_off (exclusive) --------
__global__ __launch_bounds__(1024) void k_scan1() {
    __shared__ int warps[32];
    int tid = threadIdx.x, lane = tid & 31, wid = tid >> 5;
    int carry = 0;
    for (int base = 0; base < NN; base += 1024) {
        int idx = base + tid;
        int v = (idx < NN) ? g_cnt[idx] : 0;
        int x = v;
        #pragma unroll
        for (int o = 1; o < 32; o <<= 1) {
            int y = __shfl_up_sync(0xffffffffu, x, o);
            if (lane >= o) x += y;
        }
        if (lane == 31) warps[wid] = x;
        __syncthreads();
        if (wid == 0) {
            int wv = warps[lane];
            #pragma unroll
            for (int o = 1; o < 32; o <<= 1) {
                int y = __shfl_up_sync(0xffffffffu, wv, o);
                if (lane >= o) wv += y;
            }
            warps[lane] = wv;
        }
        __syncthreads();
        int pre = (wid > 0) ? warps[wid - 1] : 0;
        if (idx < NN) g_off[idx] = carry + pre + x - v;
        carry += warps[31];
        __syncthreads();
    }
}

// ---------------- K4 (PROFILED): edge logits + fused CSR scatter ----------------
__global__ void k_edge1(const float* __restrict__ ef,
                        const int* __restrict__ src,
                        const int* __restrict__ dst) {
    __shared__ float Vs[F_EDGE * NH];
    if (threadIdx.x < 256) Vs[threadIdx.x] = g_V[threadIdx.x];
    __syncthreads();
    int t = blockIdx.x * blockDim.x + threadIdx.x;
    int e = t >> 3, sub = t & 7;
    int lane = threadIdx.x & 31;
    if (e >= EE) return;
    const float4* p4 = (const float4*)&ef[e * 64 + sub * 8];
    float4 x0 = p4[0], x1 = p4[1];
    float xs[8] = {x0.x, x0.y, x0.z, x0.w, x1.x, x1.y, x1.z, x1.w};
    float a0 = 0.f, a1 = 0.f, a2 = 0.f, a3 = 0.f;
    #pragma unroll
    for (int j = 0; j < 8; j++) {
        float4 v = *(const float4*)&Vs[(sub * 8 + j) * 4];
        a0 += xs[j] * v.x; a1 += xs[j] * v.y; a2 += xs[j] * v.z; a3 += xs[j] * v.w;
    }
    #pragma unroll
    for (int off = 4; off; off >>= 1) {
        a0 += __shfl_xor_sync(0xffffffffu, a0, off);
        a1 += __shfl_xor_sync(0xffffffffu, a1, off);
        a2 += __shfl_xor_sync(0xffffffffu, a2, off);
        a3 += __shfl_xor_sync(0xffffffffu, a3, off);
    }
    int s = src[e], dd = dst[e];
    int p = 0;
    if (sub == 0) p = g_off[dd] + atomicAdd(&g_cur[dd], 1);
    p = __shfl_sync(0xffffffffu, p, lane & ~7);
    if (sub == 0) g_esrc[p] = s;
    if (sub < 4) {
        int h = sub;
        float ee = (h == 0) ? a0 : (h == 1) ? a1 : (h == 2) ? a2 : a3;
        float v = g_el[s * 4 + h] + g_er[dd * 4 + h] + ee;
        v = (v > 0.0f) ? v : NEG_SLOPE * v;
        g_eex[p * 4 + h] = __expf(v);
    }
}

// ---------------- K5: block-per-node gather-reduce + norms + residual + reset --
__global__ __launch_bounds__(128) void k_agg(float* __restrict__ out) {
    __shared__ int   ssrc[32];
    __shared__ float sex[32 * 4];
    __shared__ float sacc[4][256];
    __shared__ float ssum[4][NH];
    int n = blockIdx.x;
    int tid = threadIdx.x;
    int w = tid >> 5, lane = tid & 31;
    int h = lane >> 3;                  // head for dims lane*8..lane*8+7
    int beg = g_off[n];
    int deg = g_cnt[n];

    float acc[8];
    #pragma unroll
    for (int r = 0; r < 8; r++) acc[r] = 0.0f;
    float sum_ex = 0.0f;                // per-head partial (head = h)

    for (int base = 0; base < deg; base += 32) {
        int chunk = min(32, deg - base);
        if (tid < chunk) ssrc[tid] = g_esrc[beg + base + tid];
        if (tid < chunk * 4) sex[tid] = g_eex[(beg + base) * 4 + tid];
        __syncthreads();

        int i = w;
        uint4 v = make_uint4(0, 0, 0, 0);
        float ex = 0.0f;
        if (i < chunk) {
            int s = ssrc[i];
            ex = sex[i * 4 + h];
            v = *(const uint4*)&g_featb[s * 128 + lane * 4];
        }
        while (i < chunk) {
            int ni = i + 4;
            uint4 nv = make_uint4(0, 0, 0, 0);
            float nex = 0.0f;
            if (ni < chunk) {
                int ns = ssrc[ni];
                nex = sex[ni * 4 + h];
                nv = *(const uint4*)&g_featb[ns * 128 + lane * 4];
            }
            float2 f0 = __bfloat1622float2(*(__nv_bfloat162*)&v.x);
            float2 f1 = __bfloat1622float2(*(__nv_bfloat162*)&v.y);
            float2 f2 = __bfloat1622float2(*(__nv_bfloat162*)&v.z);
            float2 f3 = __bfloat1622float2(*(__nv_bfloat162*)&v.w);
            acc[0] += ex * f0.x; acc[1] += ex * f0.y;
            acc[2] += ex * f1.x; acc[3] += ex * f1.y;
            acc[4] += ex * f2.x; acc[5] += ex * f2.y;
            acc[6] += ex * f3.x; acc[7] += ex * f3.y;
            sum_ex += ex;
            v = nv; ex = nex; i = ni;
        }
        __syncthreads();
    }

    #pragma unroll
    for (int r = 0; r < 8; r++) sacc[w][lane * 8 + r] = acc[r];
    if ((lane & 7) == 0) ssum[w][h] = sum_ex;
    __syncthreads();

    // restore zero-invariant for next run (all reads of cnt/cur are done)
    if (tid == 0) { g_cnt[n] = 0; g_cur[n] = 0; }

    int h2 = tid >> 5;                  // head of output dims 2*tid, 2*tid+1
    float tot = ssum[0][h2] + ssum[1][h2] + ssum[2][h2] + ssum[3][h2];
    float invd = 1.0f / fmaxf((float)deg, 1.0f);
    float inv_ex = (tot > 0.0f) ? (1.0f / tot) : 0.0f;
    float sc = inv_ex * invd;

    int d0 = tid * 2;
    float vx = sacc[0][d0] + sacc[1][d0] + sacc[2][d0] + sacc[3][d0];
    float vy = sacc[0][d0+1] + sacc[1][d0+1] + sacc[2][d0+1] + sacc[3][d0+1];
    float2 rs = *(const float2*)&g_res[n * HD + d0];
    *(float2*)&out[n * HD + d0] = make_float2(vx * sc + rs.x, vy * sc + rs.y);
}

// ---------------- launch ----------------
extern "C" void kernel_launch(void* const* d_in, const int* in_sizes, int n_in,
                              void* d_out, int out_size) {
    const float* h_in    = (const float*)d_in[0];
    const float* ef      = (const float*)d_in[1];
    const int*   src     = (const int*)d_in[2];
    const int*   dst     = (const int*)d_in[3];
    const float* W_fc    = (const float*)d_in[4];
    const float* W_edge  = (const float*)d_in[5];
    const float* W_res   = (const float*)d_in[6];
    const float* attn_l  = (const float*)d_in[7];
    const float* attn_r  = (const float*)d_in[8];
    const float* attn_e  = (const float*)d_in[9];
    float* out = (float*)d_out;

    k_pre<<<(EE + 255) / 256, 256>>>(W_edge, attn_e, dst);          // 1

    dim3 ggrid(4, (NN + GBM - 1) / GBM);
    k_gemm_attn<<<ggrid, 256>>>(h_in, W_fc, W_res, attn_l, attn_r); // 2

    k_scan1<<<1, 1024>>>();                                         // 3

    k_edge1<<<(EE * 8 + 255) / 256, 256>>>(ef, src, dst);           // 4 (profiled)

    k_agg<<<NN, 128>>>(out);                                        // 5
}

// round 14
// speedup vs baseline: 1.3239x; 1.3239x over previous
#include <cuda_runtime.h>
#include <cuda_bf16.h>

#define NN 50000
#define EE 800000
#define F_INN 256
#define F_EDGE 64
#define NH 4
#define ND 64
#define HD 256
#define NEG_SLOPE 0.2f

// ---------------- scratch (static device globals; no allocation) ----------------
// invariant: g_cnt / g_cur are all-zero before every kernel_launch call
// (zero-init at load; k_agg restores them at the end of each run)
__device__ __nv_bfloat162 g_featb[NN * 128]; // h @ W_fc^T in bf16 pairs
__device__ float g_res[NN * HD];             // h @ W_res^T
__device__ float g_el[NN * NH];
__device__ float g_er[NN * NH];
__device__ float g_V[F_EDGE * NH];           // collapsed W_edge x attn_e, layout [j][h]
__device__ int   g_cnt[NN];                  // in-degree
__device__ int   g_off[NN];                  // CSR offsets (exclusive scan of cnt)
__device__ int   g_cur[NN];                  // scatter cursors
__device__ int   g_esrc[EE];                 // CSR: src node per slot
__device__ float g_eex[EE * NH];             // CSR: exp(e) per slot, 4 heads

// ---------------- helpers ----------------
__device__ __forceinline__ unsigned f2tf32(float f) {
    unsigned u;
    asm("cvt.rna.tf32.f32 %0, %1;" : "=r"(u) : "f"(f));
    return u;
}

__device__ __forceinline__ void mma_tf32(float& c0, float& c1, float& c2, float& c3,
                                         unsigned a0, unsigned a1, unsigned a2, unsigned a3,
                                         unsigned b0, unsigned b1) {
    asm volatile("mma.sync.aligned.m16n8k8.row.col.f32.tf32.tf32.f32 "
                 "{%0,%1,%2,%3}, {%4,%5,%6,%7}, {%8,%9}, {%0,%1,%2,%3};"
                 : "+f"(c0), "+f"(c1), "+f"(c2), "+f"(c3)
                 : "r"(a0), "r"(a1), "r"(a2), "r"(a3), "r"(b0), "r"(b1));
}

__device__ __forceinline__ void cp16(float* smem, const float* gmem) {
    unsigned s = (unsigned)__cvta_generic_to_shared(smem);
    asm volatile("cp.async.cg.shared.global [%0], [%1], 16;" :: "r"(s), "l"(gmem));
}

// ---------------- K1: prep V (block 0) + degree count ----------------
__global__ void k_pre(const float* __restrict__ W_edge, const float* __restrict__ attn_e,
                      const int* __restrict__ dst) {
    if (blockIdx.x == 0 && threadIdx.x < 256) {
        int j = threadIdx.x & 63, h = threadIdx.x >> 6;
        float s = 0.0f;
        #pragma unroll 8
        for (int d = 0; d < 64; d++)
            s += W_edge[(h * 64 + d) * 64 + j] * attn_e[h * 64 + d];
        g_V[j * 4 + h] = s;
    }
    int e = blockIdx.x * blockDim.x + threadIdx.x;
    if (e < EE) atomicAdd(&g_cnt[dst[e]], 1);
}

// ---------------- K2: tf32 GEMM (cp.async, cvt.rna) + fused el/er epilogue ----
#define GBM 128
#define GBN 128
#define GBK 16
#define KT  (F_INN / GBK)   // 16
#define SPAD 20             // words per row; conflict-free frag loads

__global__ __launch_bounds__(256) void k_gemm_attn(const float* __restrict__ A,
                                                   const float* __restrict__ Wfc,
                                                   const float* __restrict__ Wres,
                                                   const float* __restrict__ attn_l,
                                                   const float* __restrict__ attn_r) {
    __shared__ float As[2][GBM * SPAD];
    __shared__ float Bs[2][GBN * SPAD];
    __shared__ float sdotL[512];
    __shared__ float sdotR[512];

    const int colbase = blockIdx.x * GBN;    // 0,128,256,384
    const int rowbase = blockIdx.y * GBM;
    const bool isfeat = (colbase < 256);
    const float* Bsrc = isfeat ? (Wfc + colbase * F_INN)
                               : (Wres + (colbase - 256) * F_INN);
    const int ccol0 = isfeat ? colbase : colbase - 256;

    const int tid  = threadIdx.x;
    const int w    = tid >> 5;
    const int lane = tid & 31;
    const int grp  = lane >> 2;     // 0..7
    const int tg   = lane & 3;      // 0..3
    const int wm   = w & 1;
    const int wn   = w >> 1;

    const int lr  = tid >> 2;          // 0..63 (+64 on second pass)
    const int lc4 = (tid & 3) * 4;     // 0,4,8,12

    float acc[4][4][4];
    #pragma unroll
    for (int mt = 0; mt < 4; mt++)
        #pragma unroll
        for (int nt = 0; nt < 4; nt++)
            #pragma unroll
            for (int r = 0; r < 4; r++) acc[mt][nt][r] = 0.0f;

    auto issue = [&](int kt, int buf) {
        int kk = kt * GBK;
        #pragma unroll
        for (int i = 0; i < 2; i++) {
            int r = lr + i * 64;
            int gr = rowbase + r;
            if (gr >= NN) gr = NN - 1;   // clamp; garbage rows never stored
            cp16(&As[buf][r * SPAD + lc4], &A[gr * F_INN + kk + lc4]);
            cp16(&Bs[buf][r * SPAD + lc4], &Bsrc[r * F_INN + kk + lc4]);
        }
    };

    issue(0, 0);
    asm volatile("cp.async.commit_group;");

    for (int kt = 0; kt < KT; kt++) {
        int buf = kt & 1;
        if (kt + 1 < KT) {
            issue(kt + 1, (kt + 1) & 1);
            asm volatile("cp.async.commit_group;");
            asm volatile("cp.async.wait_group 1;");
        } else {
            asm volatile("cp.async.wait_group 0;");
        }
        __syncthreads();

        #pragma unroll
        for (int ks = 0; ks < 2; ks++) {
            const int kof = ks * 8 + tg;
            unsigned af[4][4];
            #pragma unroll
            for (int mt = 0; mt < 4; mt++) {
                int r0 = wm * 64 + mt * 16 + grp;
                af[mt][0] = f2tf32(As[buf][r0 * SPAD + kof]);
                af[mt][1] = f2tf32(As[buf][(r0 + 8) * SPAD + kof]);
                af[mt][2] = f2tf32(As[buf][r0 * SPAD + kof + 4]);
                af[mt][3] = f2tf32(As[buf][(r0 + 8) * SPAD + kof + 4]);
            }
            unsigned bf[4][2];
            #pragma unroll
            for (int nt = 0; nt < 4; nt++) {
                int c0 = wn * 32 + nt * 8 + grp;
                bf[nt][0] = f2tf32(Bs[buf][c0 * SPAD + kof]);
                bf[nt][1] = f2tf32(Bs[buf][c0 * SPAD + kof + 4]);
            }
            #pragma unroll
            for (int mt = 0; mt < 4; mt++)
                #pragma unroll
                for (int nt = 0; nt < 4; nt++)
                    mma_tf32(acc[mt][nt][0], acc[mt][nt][1], acc[mt][nt][2], acc[mt][nt][3],
                             af[mt][0], af[mt][1], af[mt][2], af[mt][3],
                             bf[nt][0], bf[nt][1]);
        }
        __syncthreads();
    }

    // ---- store C ----
    #pragma unroll
    for (int mt = 0; mt < 4; mt++) {
        int row0 = rowbase + wm * 64 + mt * 16 + grp;
        int row1 = row0 + 8;
        #pragma unroll
        for (int nt = 0; nt < 4; nt++) {
            int col = ccol0 + wn * 32 + nt * 8 + 2 * tg;
            if (isfeat) {
                if (row0 < NN)
                    g_featb[row0 * 128 + (col >> 1)] =
                        __floats2bfloat162_rn(acc[mt][nt][0], acc[mt][nt][1]);
                if (row1 < NN)
                    g_featb[row1 * 128 + (col >> 1)] =
                        __floats2bfloat162_rn(acc[mt][nt][2], acc[mt][nt][3]);
            } else {
                if (row0 < NN)
                    *(float2*)&g_res[row0 * HD + col] = make_float2(acc[mt][nt][0], acc[mt][nt][1]);
                if (row1 < NN)
                    *(float2*)&g_res[row1 * HD + col] = make_float2(acc[mt][nt][2], acc[mt][nt][3]);
            }
        }
    }

    // ---- fused attention dots (feat blocks only) ----
    if (isfeat) {
        float al[4][2], ar[4][2];
        #pragma unroll
        for (int nt = 0; nt < 4; nt++) {
            int gc = colbase + wn * 32 + nt * 8 + 2 * tg;
            al[nt][0] = attn_l[gc]; al[nt][1] = attn_l[gc + 1];
            ar[nt][0] = attn_r[gc]; ar[nt][1] = attn_r[gc + 1];
        }
        #pragma unroll
        for (int mt = 0; mt < 4; mt++) {
            float pl0 = 0.f, pl1 = 0.f, pr0 = 0.f, pr1 = 0.f;
            #pragma unroll
            for (int nt = 0; nt < 4; nt++) {
                pl0 += acc[mt][nt][0] * al[nt][0] + acc[mt][nt][1] * al[nt][1];
                pl1 += acc[mt][nt][2] * al[nt][0] + acc[mt][nt][3] * al[nt][1];
                pr0 += acc[mt][nt][0] * ar[nt][0] + acc[mt][nt][1] * ar[nt][1];
                pr1 += acc[mt][nt][2] * ar[nt][0] + acc[mt][nt][3] * ar[nt][1];
            }
            #pragma unroll
            for (int o = 2; o; o >>= 1) {
                pl0 += __shfl_down_sync(0xffffffffu, pl0, o, 4);
                pl1 += __shfl_down_sync(0xffffffffu, pl1, o, 4);
                pr0 += __shfl_down_sync(0xffffffffu, pr0, o, 4);
                pr1 += __shfl_down_sync(0xffffffffu, pr1, o, 4);
            }
            if (tg == 0) {
                int hb = wn >> 1, wlo = wn & 1;
                int base = ((((wm * 2 + hb) * 2 + wlo) * 4 + mt) * 8 + grp) * 2;
                sdotL[base + 0] = pl0; sdotL[base + 1] = pl1;
                sdotR[base + 0] = pr0; sdotR[base + 1] = pr1;
            }
        }
        __syncthreads();
        int t = tid;
        int rhalf = t & 1, grp2 = (t >> 1) & 7, mt2 = (t >> 4) & 3;
        int hb2 = (t >> 6) & 1, wm2 = (t >> 7) & 1;
        int i0 = ((((wm2 * 2 + hb2) * 2 + 0) * 4 + mt2) * 8 + grp2) * 2 + rhalf;
        int i1 = ((((wm2 * 2 + hb2) * 2 + 1) * 4 + mt2) * 8 + grp2) * 2 + rhalf;
        int row = rowbase + wm2 * 64 + mt2 * 16 + rhalf * 8 + grp2;
        int headg = (colbase >> 6) + hb2;
        if (row < NN) {
            g_el[row * 4 + headg] = sdotL[i0] + sdotL[i1];
            g_er[row * 4 + headg] = sdotR[i0] + sdotR[i1];
        }
    }
}

// ---------------- K3: single-block scan of g_cnt -> g_off (exclusive) --------
__global__ __launch_bounds__(1024) void k_scan1() {
    __shared__ int warps[32];
    int tid = threadIdx.x, lane = tid & 31, wid = tid >> 5;
    int carry = 0;
    for (int base = 0; base < NN; base += 1024) {
        int idx = base + tid;
        int v = (idx < NN) ? g_cnt[idx] : 0;
        int x = v;
        #pragma unroll
        for (int o = 1; o < 32; o <<= 1) {
            int y = __shfl_up_sync(0xffffffffu, x, o);
            if (lane >= o) x += y;
        }
        if (lane == 31) warps[wid] = x;
        __syncthreads();
        if (wid == 0) {
            int wv = warps[lane];
            #pragma unroll
            for (int o = 1; o < 32; o <<= 1) {
                int y = __shfl_up_sync(0xffffffffu, wv, o);
                if (lane >= o) wv += y;
            }
            warps[lane] = wv;
        }
        __syncthreads();
        int pre = (wid > 0) ? warps[wid - 1] : 0;
        if (idx < NN) g_off[idx] = carry + pre + x - v;
        carry += warps[31];
        __syncthreads();
    }
}

// ---------------- K4 (PROFILED): edge logits + CSR scatter, V in registers ----
#define E_PER_WARP 64
#define E1_BLOCKS ((EE + 8 * E_PER_WARP - 1) / (8 * E_PER_WARP))   // 1563

__global__ __launch_bounds__(256) void k_edge1(const float* __restrict__ ef,
                                               const int* __restrict__ src,
                                               const int* __restrict__ dst) {
    int lane = threadIdx.x & 31;
    int warp = threadIdx.x >> 5;
    int sub = lane & 7, grp4 = lane >> 3;

    // V slice in registers: this thread covers V rows sub*8 .. sub*8+7
    float4 vreg[8];
    #pragma unroll
    for (int j = 0; j < 8; j++)
        vreg[j] = *(const float4*)&g_V[(sub * 8 + j) * 4];

    int ebase = (blockIdx.x * 8 + warp) * E_PER_WARP + grp4;

    #pragma unroll 2
    for (int it = 0; it < E_PER_WARP / 4; it++) {
        int e = ebase + it * 4;
        bool valid = (e < EE);
        int ec = valid ? e : (EE - 1);          // clamp to keep warp converged

        const float4* p4 = (const float4*)&ef[(long)ec * 64 + sub * 8];
        float4 x0 = p4[0], x1 = p4[1];
        float xs[8] = {x0.x, x0.y, x0.z, x0.w, x1.x, x1.y, x1.z, x1.w};
        float a0 = 0.f, a1 = 0.f, a2 = 0.f, a3 = 0.f;
        #pragma unroll
        for (int j = 0; j < 8; j++) {
            a0 += xs[j] * vreg[j].x; a1 += xs[j] * vreg[j].y;
            a2 += xs[j] * vreg[j].z; a3 += xs[j] * vreg[j].w;
        }
        #pragma unroll
        for (int off = 4; off; off >>= 1) {
            a0 += __shfl_xor_sync(0xffffffffu, a0, off);
            a1 += __shfl_xor_sync(0xffffffffu, a1, off);
            a2 += __shfl_xor_sync(0xffffffffu, a2, off);
            a3 += __shfl_xor_sync(0xffffffffu, a3, off);
        }
        int s = src[ec], dd = dst[ec];
        int p = 0;
        if (sub == 0 && valid) p = g_off[dd] + atomicAdd(&g_cur[dd], 1);
        p = __shfl_sync(0xffffffffu, p, lane & ~7);
        if (valid) {
            if (sub == 0) g_esrc[p] = s;
            if (sub < 4) {
                int h = sub;
                float ee = (h == 0) ? a0 : (h == 1) ? a1 : (h == 2) ? a2 : a3;
                float v = g_el[s * 4 + h] + g_er[dd * 4 + h] + ee;
                v = (v > 0.0f) ? v : NEG_SLOPE * v;
                g_eex[p * 4 + h] = __expf(v);
            }
        }
    }
}

// ---------------- K5: block-per-node gather-reduce + norms + residual + reset --
__global__ __launch_bounds__(128) void k_agg(float* __restrict__ out) {
    __shared__ int   ssrc[32];
    __shared__ float sex[32 * 4];
    __shared__ float sacc[4][256];
    __shared__ float ssum[4][NH];
    int n = blockIdx.x;
    int tid = threadIdx.x;
    int w = tid >> 5, lane = tid & 31;
    int h = lane >> 3;                  // head for dims lane*8..lane*8+7
    int beg = g_off[n];
    int deg = g_cnt[n];

    float acc[8];
    #pragma unroll
    for (int r = 0; r < 8; r++) acc[r] = 0.0f;
    float sum_ex = 0.0f;                // per-head partial (head = h)

    for (int base = 0; base < deg; base += 32) {
        int chunk = min(32, deg - base);
        if (tid < chunk) ssrc[tid] = g_esrc[beg + base + tid];
        if (tid < chunk * 4) sex[tid] = g_eex[(beg + base) * 4 + tid];
        __syncthreads();

        int i = w;
        uint4 v = make_uint4(0, 0, 0, 0);
        float ex = 0.0f;
        if (i < chunk) {
            int s = ssrc[i];
            ex = sex[i * 4 + h];
            v = *(const uint4*)&g_featb[s * 128 + lane * 4];
        }
        while (i < chunk) {
            int ni = i + 4;
            uint4 nv = make_uint4(0, 0, 0, 0);
            float nex = 0.0f;
            if (ni < chunk) {
                int ns = ssrc[ni];
                nex = sex[ni * 4 + h];
                nv = *(const uint4*)&g_featb[ns * 128 + lane * 4];
            }
            float2 f0 = __bfloat1622float2(*(__nv_bfloat162*)&v.x);
            float2 f1 = __bfloat1622float2(*(__nv_bfloat162*)&v.y);
            float2 f2 = __bfloat1622float2(*(__nv_bfloat162*)&v.z);
            float2 f3 = __bfloat1622float2(*(__nv_bfloat162*)&v.w);
            acc[0] += ex * f0.x; acc[1] += ex * f0.y;
            acc[2] += ex * f1.x; acc[3] += ex * f1.y;
            acc[4] += ex * f2.x; acc[5] += ex * f2.y;
            acc[6] += ex * f3.x; acc[7] += ex * f3.y;
            sum_ex += ex;
            v = nv; ex = nex; i = ni;
        }
        __syncthreads();
    }

    #pragma unroll
    for (int r = 0; r < 8; r++) sacc[w][lane * 8 + r] = acc[r];
    if ((lane & 7) == 0) ssum[w][h] = sum_ex;
    __syncthreads();

    // restore zero-invariant for next run (all reads of cnt/cur are done)
    if (tid == 0) { g_cnt[n] = 0; g_cur[n] = 0; }

    int h2 = tid >> 5;                  // head of output dims 2*tid, 2*tid+1
    float tot = ssum[0][h2] + ssum[1][h2] + ssum[2][h2] + ssum[3][h2];
    float invd = 1.0f / fmaxf((float)deg, 1.0f);
    float inv_ex = (tot > 0.0f) ? (1.0f / tot) : 0.0f;
    float sc = inv_ex * invd;

    int d0 = tid * 2;
    float vx = sacc[0][d0] + sacc[1][d0] + sacc[2][d0] + sacc[3][d0];
    float vy = sacc[0][d0+1] + sacc[1][d0+1] + sacc[2][d0+1] + sacc[3][d0+1];
    float2 rs = *(const float2*)&g_res[n * HD + d0];
    *(float2*)&out[n * HD + d0] = make_float2(vx * sc + rs.x, vy * sc + rs.y);
}

// ---------------- launch ----------------
extern "C" void kernel_launch(void* const* d_in, const int* in_sizes, int n_in,
                              void* d_out, int out_size) {
    const float* h_in    = (const float*)d_in[0];
    const float* ef      = (const float*)d_in[1];
    const int*   src     = (const int*)d_in[2];
    const int*   dst     = (const int*)d_in[3];
    const float* W_fc    = (const float*)d_in[4];
    const float* W_edge  = (const float*)d_in[5];
    const float* W_res   = (const float*)d_in[6];
    const float* attn_l  = (const float*)d_in[7];
    const float* attn_r  = (const float*)d_in[8];
    const float* attn_e  = (const float*)d_in[9];
    float* out = (float*)d_out;

    k_pre<<<(EE + 255) / 256, 256>>>(W_edge, attn_e, dst);          // 1

    dim3 ggrid(4, (NN + GBM - 1) / GBM);
    k_gemm_attn<<<ggrid, 256>>>(h_in, W_fc, W_res, attn_l, attn_r); // 2

    k_scan1<<<1, 1024>>>();                                         // 3

    k_edge1<<<E1_BLOCKS, 256>>>(ef, src, dst);                      // 4 (profiled)

    k_agg<<<NN, 128>>>(out);                                        // 5
}

// round 15
// speedup vs baseline: 1.3970x; 1.0552x over previous
#include <cuda_runtime.h>
#include <cuda_bf16.h>

#define NN 50000
#define EE 800000
#define F_INN 256
#define F_EDGE 64
#define NH 4
#define ND 64
#define HD 256
#define NEG_SLOPE 0.2f

// ---------------- scratch (static device globals; no allocation) ----------------
// invariant: g_cnt / g_cur are all-zero before every kernel_launch call
// (zero-init at load; k_agg restores them at the end of each run)
__device__ __nv_bfloat162 g_featb[NN * 128]; // h @ W_fc^T in bf16 pairs
__device__ float g_res[NN * HD];             // h @ W_res^T
__device__ float g_el[NN * NH];
__device__ float g_er[NN * NH];
__device__ float g_V[F_EDGE * NH];           // collapsed W_edge x attn_e, layout [j][h]
__device__ int   g_cnt[NN];                  // in-degree
__device__ int   g_off[NN];                  // CSR offsets (exclusive scan of cnt)
__device__ int   g_cur[NN];                  // scatter cursors
__device__ int   g_esrc[EE];                 // CSR: src node per slot
__device__ float g_eex[EE * NH];             // CSR: exp(e) per slot, 4 heads

// ---------------- helpers ----------------
__device__ __forceinline__ unsigned f2tf32(float f) {
    unsigned u;
    asm("cvt.rna.tf32.f32 %0, %1;" : "=r"(u) : "f"(f));
    return u;
}

__device__ __forceinline__ void mma_tf32(float& c0, float& c1, float& c2, float& c3,
                                         unsigned a0, unsigned a1, unsigned a2, unsigned a3,
                                         unsigned b0, unsigned b1) {
    asm volatile("mma.sync.aligned.m16n8k8.row.col.f32.tf32.tf32.f32 "
                 "{%0,%1,%2,%3}, {%4,%5,%6,%7}, {%8,%9}, {%0,%1,%2,%3};"
                 : "+f"(c0), "+f"(c1), "+f"(c2), "+f"(c3)
                 : "r"(a0), "r"(a1), "r"(a2), "r"(a3), "r"(b0), "r"(b1));
}

__device__ __forceinline__ void cp16(float* smem, const float* gmem) {
    unsigned s = (unsigned)__cvta_generic_to_shared(smem);
    asm volatile("cp.async.cg.shared.global [%0], [%1], 16;" :: "r"(s), "l"(gmem));
}

// ---------------- K1: tf32 GEMM + fused el/er epilogue + fused degree count ---
#define GBM 128
#define GBN 128
#define GBK 16
#define KT  (F_INN / GBK)   // 16
#define SPAD 20             // words per row; conflict-free frag loads

__global__ __launch_bounds__(256) void k_gemm_attn(const float* __restrict__ A,
                                                   const float* __restrict__ Wfc,
                                                   const float* __restrict__ Wres,
                                                   const float* __restrict__ attn_l,
                                                   const float* __restrict__ attn_r,
                                                   const int* __restrict__ dstp) {
    __shared__ float As[2][GBM * SPAD];
    __shared__ float Bs[2][GBN * SPAD];
    __shared__ float sdotL[512];
    __shared__ float sdotR[512];

    const int colbase = blockIdx.x * GBN;    // 0,128,256,384
    const int rowbase = blockIdx.y * GBM;
    const bool isfeat = (colbase < 256);
    const float* Bsrc = isfeat ? (Wfc + colbase * F_INN)
                               : (Wres + (colbase - 256) * F_INN);
    const int ccol0 = isfeat ? colbase : colbase - 256;

    const int tid  = threadIdx.x;
    const int w    = tid >> 5;
    const int lane = tid & 31;
    const int grp  = lane >> 2;     // 0..7
    const int tg   = lane & 3;      // 0..3
    const int wm   = w & 1;
    const int wn   = w >> 1;

    const int lr  = tid >> 2;          // 0..63 (+64 on second pass)
    const int lc4 = (tid & 3) * 4;     // 0,4,8,12

    float acc[4][4][4];
    #pragma unroll
    for (int mt = 0; mt < 4; mt++)
        #pragma unroll
        for (int nt = 0; nt < 4; nt++)
            #pragma unroll
            for (int r = 0; r < 4; r++) acc[mt][nt][r] = 0.0f;

    auto issue = [&](int kt, int buf) {
        int kk = kt * GBK;
        #pragma unroll
        for (int i = 0; i < 2; i++) {
            int r = lr + i * 64;
            int gr = rowbase + r;
            if (gr >= NN) gr = NN - 1;   // clamp; garbage rows never stored
            cp16(&As[buf][r * SPAD + lc4], &A[gr * F_INN + kk + lc4]);
            cp16(&Bs[buf][r * SPAD + lc4], &Bsrc[r * F_INN + kk + lc4]);
        }
    };

    issue(0, 0);
    asm volatile("cp.async.commit_group;");

    // fused degree count: this block's 512-edge slice, overlapped with stage-0 DMA
    {
        int blin = blockIdx.y * 4 + blockIdx.x;     // 0..1563
        int e0 = blin * 512 + tid;
        if (e0 < EE) atomicAdd(&g_cnt[dstp[e0]], 1);
        if (e0 + 256 < EE) atomicAdd(&g_cnt[dstp[e0 + 256]], 1);
    }

    for (int kt = 0; kt < KT; kt++) {
        int buf = kt & 1;
        if (kt + 1 < KT) {
            issue(kt + 1, (kt + 1) & 1);
            asm volatile("cp.async.commit_group;");
            asm volatile("cp.async.wait_group 1;");
        } else {
            asm volatile("cp.async.wait_group 0;");
        }
        __syncthreads();

        #pragma unroll
        for (int ks = 0; ks < 2; ks++) {
            const int kof = ks * 8 + tg;
            unsigned af[4][4];
            #pragma unroll
            for (int mt = 0; mt < 4; mt++) {
                int r0 = wm * 64 + mt * 16 + grp;
                af[mt][0] = f2tf32(As[buf][r0 * SPAD + kof]);
                af[mt][1] = f2tf32(As[buf][(r0 + 8) * SPAD + kof]);
                af[mt][2] = f2tf32(As[buf][r0 * SPAD + kof + 4]);
                af[mt][3] = f2tf32(As[buf][(r0 + 8) * SPAD + kof + 4]);
            }
            unsigned bf[4][2];
            #pragma unroll
            for (int nt = 0; nt < 4; nt++) {
                int c0 = wn * 32 + nt * 8 + grp;
                bf[nt][0] = f2tf32(Bs[buf][c0 * SPAD + kof]);
                bf[nt][1] = f2tf32(Bs[buf][c0 * SPAD + kof + 4]);
            }
            #pragma unroll
            for (int mt = 0; mt < 4; mt++)
                #pragma unroll
                for (int nt = 0; nt < 4; nt++)
                    mma_tf32(acc[mt][nt][0], acc[mt][nt][1], acc[mt][nt][2], acc[mt][nt][3],
                             af[mt][0], af[mt][1], af[mt][2], af[mt][3],
                             bf[nt][0], bf[nt][1]);
        }
        __syncthreads();
    }

    // ---- store C ----
    #pragma unroll
    for (int mt = 0; mt < 4; mt++) {
        int row0 = rowbase + wm * 64 + mt * 16 + grp;
        int row1 = row0 + 8;
        #pragma unroll
        for (int nt = 0; nt < 4; nt++) {
            int col = ccol0 + wn * 32 + nt * 8 + 2 * tg;
            if (isfeat) {
                if (row0 < NN)
                    g_featb[row0 * 128 + (col >> 1)] =
                        __floats2bfloat162_rn(acc[mt][nt][0], acc[mt][nt][1]);
                if (row1 < NN)
                    g_featb[row1 * 128 + (col >> 1)] =
                        __floats2bfloat162_rn(acc[mt][nt][2], acc[mt][nt][3]);
            } else {
                if (row0 < NN)
                    *(float2*)&g_res[row0 * HD + col] = make_float2(acc[mt][nt][0], acc[mt][nt][1]);
                if (row1 < NN)
                    *(float2*)&g_res[row1 * HD + col] = make_float2(acc[mt][nt][2], acc[mt][nt][3]);
            }
        }
    }

    // ---- fused attention dots (feat blocks only) ----
    if (isfeat) {
        float al[4][2], ar[4][2];
        #pragma unroll
        for (int nt = 0; nt < 4; nt++) {
            int gc = colbase + wn * 32 + nt * 8 + 2 * tg;
            al[nt][0] = attn_l[gc]; al[nt][1] = attn_l[gc + 1];
            ar[nt][0] = attn_r[gc]; ar[nt][1] = attn_r[gc + 1];
        }
        #pragma unroll
        for (int mt = 0; mt < 4; mt++) {
            float pl0 = 0.f, pl1 = 0.f, pr0 = 0.f, pr1 = 0.f;
            #pragma unroll
            for (int nt = 0; nt < 4; nt++) {
                pl0 += acc[mt][nt][0] * al[nt][0] + acc[mt][nt][1] * al[nt][1];
                pl1 += acc[mt][nt][2] * al[nt][0] + acc[mt][nt][3] * al[nt][1];
                pr0 += acc[mt][nt][0] * ar[nt][0] + acc[mt][nt][1] * ar[nt][1];
                pr1 += acc[mt][nt][2] * ar[nt][0] + acc[mt][nt][3] * ar[nt][1];
            }
            #pragma unroll
            for (int o = 2; o; o >>= 1) {
                pl0 += __shfl_down_sync(0xffffffffu, pl0, o, 4);
                pl1 += __shfl_down_sync(0xffffffffu, pl1, o, 4);
                pr0 += __shfl_down_sync(0xffffffffu, pr0, o, 4);
                pr1 += __shfl_down_sync(0xffffffffu, pr1, o, 4);
            }
            if (tg == 0) {
                int hb = wn >> 1, wlo = wn & 1;
                int base = ((((wm * 2 + hb) * 2 + wlo) * 4 + mt) * 8 + grp) * 2;
                sdotL[base + 0] = pl0; sdotL[base + 1] = pl1;
                sdotR[base + 0] = pr0; sdotR[base + 1] = pr1;
            }
        }
        __syncthreads();
        int t = tid;
        int rhalf = t & 1, grp2 = (t >> 1) & 7, mt2 = (t >> 4) & 3;
        int hb2 = (t >> 6) & 1, wm2 = (t >> 7) & 1;
        int i0 = ((((wm2 * 2 + hb2) * 2 + 0) * 4 + mt2) * 8 + grp2) * 2 + rhalf;
        int i1 = ((((wm2 * 2 + hb2) * 2 + 1) * 4 + mt2) * 8 + grp2) * 2 + rhalf;
        int row = rowbase + wm2 * 64 + mt2 * 16 + rhalf * 8 + grp2;
        int headg = (colbase >> 6) + hb2;
        if (row < NN) {
            g_el[row * 4 + headg] = sdotL[i0] + sdotL[i1];
            g_er[row * 4 + headg] = sdotR[i0] + sdotR[i1];
        }
    }
}

// ---------------- K2: single-block scan of g_cnt -> g_off + V prep ----------
__global__ __launch_bounds__(1024) void k_scan1(const float* __restrict__ W_edge,
                                                const float* __restrict__ attn_e) {
    __shared__ int warps[32];
    int tid = threadIdx.x, lane = tid & 31, wid = tid >> 5;
    // V prep (threads 0-255); consumed by k_edge1 next launch
    if (tid < 256) {
        int j = tid & 63, h = tid >> 6;
        float s = 0.0f;
        #pragma unroll 8
        for (int d = 0; d < 64; d++)
            s += W_edge[(h * 64 + d) * 64 + j] * attn_e[h * 64 + d];
        g_V[j * 4 + h] = s;
    }
    int carry = 0;
    for (int base = 0; base < NN; base += 1024) {
        int idx = base + tid;
        int v = (idx < NN) ? g_cnt[idx] : 0;
        int x = v;
        #pragma unroll
        for (int o = 1; o < 32; o <<= 1) {
            int y = __shfl_up_sync(0xffffffffu, x, o);
            if (lane >= o) x += y;
        }
        if (lane == 31) warps[wid] = x;
        __syncthreads();
        if (wid == 0) {
            int wv = warps[lane];
            #pragma unroll
            for (int o = 1; o < 32; o <<= 1) {
                int y = __shfl_up_sync(0xffffffffu, wv, o);
                if (lane >= o) wv += y;
            }
            warps[lane] = wv;
        }
        __syncthreads();
        int pre = (wid > 0) ? warps[wid - 1] : 0;
        if (idx < NN) g_off[idx] = carry + pre + x - v;
        carry += warps[31];
        __syncthreads();
    }
}

// ---------------- K3: edge logits + CSR scatter, V in registers ----------
#define E_PER_WARP 64
#define E1_BLOCKS ((EE + 8 * E_PER_WARP - 1) / (8 * E_PER_WARP))   // 1563

__global__ __launch_bounds__(256) void k_edge1(const float* __restrict__ ef,
                                               const int* __restrict__ src,
                                               const int* __restrict__ dst) {
    int lane = threadIdx.x & 31;
    int warp = threadIdx.x >> 5;
    int sub = lane & 7, grp4 = lane >> 3;

    float4 vreg[8];
    #pragma unroll
    for (int j = 0; j < 8; j++)
        vreg[j] = *(const float4*)&g_V[(sub * 8 + j) * 4];

    int ebase = (blockIdx.x * 8 + warp) * E_PER_WARP + grp4;

    #pragma unroll 2
    for (int it = 0; it < E_PER_WARP / 4; it++) {
        int e = ebase + it * 4;
        bool valid = (e < EE);
        int ec = valid ? e : (EE - 1);          // clamp to keep warp converged

        const float4* p4 = (const float4*)&ef[(long)ec * 64 + sub * 8];
        float4 x0 = p4[0], x1 = p4[1];
        float xs[8] = {x0.x, x0.y, x0.z, x0.w, x1.x, x1.y, x1.z, x1.w};
        float a0 = 0.f, a1 = 0.f, a2 = 0.f, a3 = 0.f;
        #pragma unroll
        for (int j = 0; j < 8; j++) {
            a0 += xs[j] * vreg[j].x; a1 += xs[j] * vreg[j].y;
            a2 += xs[j] * vreg[j].z; a3 += xs[j] * vreg[j].w;
        }
        #pragma unroll
        for (int off = 4; off; off >>= 1) {
            a0 += __shfl_xor_sync(0xffffffffu, a0, off);
            a1 += __shfl_xor_sync(0xffffffffu, a1, off);
            a2 += __shfl_xor_sync(0xffffffffu, a2, off);
            a3 += __shfl_xor_sync(0xffffffffu, a3, off);
        }
        int s = src[ec], dd = dst[ec];
        int p = 0;
        if (sub == 0 && valid) p = g_off[dd] + atomicAdd(&g_cur[dd], 1);
        p = __shfl_sync(0xffffffffu, p, lane & ~7);
        if (valid) {
            if (sub == 0) g_esrc[p] = s;
            if (sub < 4) {
                int h = sub;
                float ee = (h == 0) ? a0 : (h == 1) ? a1 : (h == 2) ? a2 : a3;
                float v = g_el[s * 4 + h] + g_er[dd * 4 + h] + ee;
                v = (v > 0.0f) ? v : NEG_SLOPE * v;
                g_eex[p * 4 + h] = __expf(v);
            }
        }
    }
}

// ---------------- K4 (PROFILED): warp-per-node gather-reduce, zero-sync -------
__global__ __launch_bounds__(256) void k_agg(float* __restrict__ out) {
    int tid = threadIdx.x;
    int w = tid >> 5, lane = tid & 31;
    int n = blockIdx.x * 8 + w;
    if (n >= NN) return;
    int h = lane >> 3;                  // head of dims lane*8..lane*8+7
    int beg = g_off[n];
    int deg = g_cnt[n];

    float acc[8];
    #pragma unroll
    for (int r = 0; r < 8; r++) acc[r] = 0.0f;
    float sum_ex = 0.0f;                // per-head (h) partial

    for (int base = 0; base < deg; base += 32) {
        int chunk = min(32, deg - base);
        int srcs = (lane < chunk) ? g_esrc[beg + base + lane] : 0;
        for (int sb = 0; sb < chunk; sb += 8) {
            int m = min(8, chunk - sb);
            float exv = (lane < m * 4) ? g_eex[(beg + base + sb) * 4 + lane] : 0.0f;

            int i = 0;
            int s = __shfl_sync(0xffffffffu, srcs, sb);
            float ex = __shfl_sync(0xffffffffu, exv, h);
            uint4 v = *(const uint4*)&g_featb[s * 128 + lane * 4];
            while (i < m) {
                int ni = i + 1;
                uint4 nv = make_uint4(0, 0, 0, 0);
                float nex = 0.0f;
                if (ni < m) {
                    int ns = __shfl_sync(0xffffffffu, srcs, sb + ni);
                    nex = __shfl_sync(0xffffffffu, exv, ni * 4 + h);
                    nv = *(const uint4*)&g_featb[ns * 128 + lane * 4];
                }
                float2 f0 = __bfloat1622float2(*(__nv_bfloat162*)&v.x);
                float2 f1 = __bfloat1622float2(*(__nv_bfloat162*)&v.y);
                float2 f2 = __bfloat1622float2(*(__nv_bfloat162*)&v.z);
                float2 f3 = __bfloat1622float2(*(__nv_bfloat162*)&v.w);
                acc[0] += ex * f0.x; acc[1] += ex * f0.y;
                acc[2] += ex * f1.x; acc[3] += ex * f1.y;
                acc[4] += ex * f2.x; acc[5] += ex * f2.y;
                acc[6] += ex * f3.x; acc[7] += ex * f3.y;
                sum_ex += ex;
                v = nv; ex = nex; i = ni;
            }
        }
    }

    // restore zero-invariant for next run
    if (lane == 0) { g_cnt[n] = 0; g_cur[n] = 0; }

    float invd = 1.0f / fmaxf((float)deg, 1.0f);
    float inv_ex = (sum_ex > 0.0f) ? (1.0f / sum_ex) : 0.0f;
    float sc = inv_ex * invd;

    const float4* rs4 = (const float4*)&g_res[n * HD + lane * 8];
    float4 r0 = rs4[0], r1 = rs4[1];
    float4 o0 = make_float4(acc[0]*sc + r0.x, acc[1]*sc + r0.y,
                            acc[2]*sc + r0.z, acc[3]*sc + r0.w);
    float4 o1 = make_float4(acc[4]*sc + r1.x, acc[5]*sc + r1.y,
                            acc[6]*sc + r1.z, acc[7]*sc + r1.w);
    float4* op = (float4*)&out[n * HD + lane * 8];
    op[0] = o0; op[1] = o1;
}

// ---------------- launch ----------------
extern "C" void kernel_launch(void* const* d_in, const int* in_sizes, int n_in,
                              void* d_out, int out_size) {
    const float* h_in    = (const float*)d_in[0];
    const float* ef      = (const float*)d_in[1];
    const int*   src     = (const int*)d_in[2];
    const int*   dst     = (const int*)d_in[3];
    const float* W_fc    = (const float*)d_in[4];
    const float* W_edge  = (const float*)d_in[5];
    const float* W_res   = (const float*)d_in[6];
    const float* attn_l  = (const float*)d_in[7];
    const float* attn_r  = (const float*)d_in[8];
    const float* attn_e  = (const float*)d_in[9];
    float* out = (float*)d_out;

    dim3 ggrid(4, (NN + GBM - 1) / GBM);
    k_gemm_attn<<<ggrid, 256>>>(h_in, W_fc, W_res, attn_l, attn_r, dst); // 1

    k_scan1<<<1, 1024>>>(W_edge, attn_e);                                // 2

    k_edge1<<<E1_BLOCKS, 256>>>(ef, src, dst);                           // 3

    k_agg<<<(NN + 7) / 8, 256>>>(out);                                   // 4 (profiled)
}

// round 16
// speedup vs baseline: 1.5232x; 1.0904x over previous
#include <cuda_runtime.h>
#include <cuda_bf16.h>

#define NN 50000
#define EE 800000
#define F_INN 256
#define F_EDGE 64
#define NH 4
#define ND 64
#define HD 256
#define NEG_SLOPE 0.2f

// ---------------- scratch (static device globals; no allocation) ----------------
// invariant: g_cnt / g_cur are all-zero before every kernel_launch call
// (zero-init at load; k_agg restores them at the end of each run)
__device__ __nv_bfloat162 g_featb[NN * 128]; // h @ W_fc^T in bf16 pairs
__device__ float g_res[NN * HD];             // h @ W_res^T
__device__ float g_el[NN * NH];
__device__ float g_er[NN * NH];
__device__ float g_V[F_EDGE * NH];           // collapsed W_edge x attn_e, layout [j][h]
__device__ int   g_cnt[NN];                  // in-degree
__device__ int   g_off[NN];                  // CSR offsets (exclusive scan of cnt)
__device__ int   g_cur[NN];                  // scatter cursors
__device__ int   g_esrc[EE];                 // CSR: src node per slot
__device__ float g_eex[EE * NH];             // CSR: exp(e) per slot, 4 heads

// ---------------- helpers ----------------
__device__ __forceinline__ unsigned f2tf32(float f) {
    unsigned u;
    asm("cvt.rna.tf32.f32 %0, %1;" : "=r"(u) : "f"(f));
    return u;
}

__device__ __forceinline__ void mma_tf32(float& c0, float& c1, float& c2, float& c3,
                                         unsigned a0, unsigned a1, unsigned a2, unsigned a3,
                                         unsigned b0, unsigned b1) {
    asm volatile("mma.sync.aligned.m16n8k8.row.col.f32.tf32.tf32.f32 "
                 "{%0,%1,%2,%3}, {%4,%5,%6,%7}, {%8,%9}, {%0,%1,%2,%3};"
                 : "+f"(c0), "+f"(c1), "+f"(c2), "+f"(c3)
                 : "r"(a0), "r"(a1), "r"(a2), "r"(a3), "r"(b0), "r"(b1));
}

__device__ __forceinline__ void cp16(float* smem, const float* gmem) {
    unsigned s = (unsigned)__cvta_generic_to_shared(smem);
    asm volatile("cp.async.cg.shared.global [%0], [%1], 16;" :: "r"(s), "l"(gmem));
}

// ---------------- K1: tf32 GEMM + fused el/er epilogue + fused degree count ---
#define GBM 128
#define GBN 128
#define GBK 16
#define KT  (F_INN / GBK)   // 16
#define SPAD 20             // words per row; conflict-free frag loads

__global__ __launch_bounds__(256) void k_gemm_attn(const float* __restrict__ A,
                                                   const float* __restrict__ Wfc,
                                                   const float* __restrict__ Wres,
                                                   const float* __restrict__ attn_l,
                                                   const float* __restrict__ attn_r,
                                                   const int* __restrict__ dstp) {
    __shared__ float As[2][GBM * SPAD];
    __shared__ float Bs[2][GBN * SPAD];
    __shared__ float sdotL[512];
    __shared__ float sdotR[512];

    const int colbase = blockIdx.x * GBN;    // 0,128,256,384
    const int rowbase = blockIdx.y * GBM;
    const bool isfeat = (colbase < 256);
    const float* Bsrc = isfeat ? (Wfc + colbase * F_INN)
                               : (Wres + (colbase - 256) * F_INN);
    const int ccol0 = isfeat ? colbase : colbase - 256;

    const int tid  = threadIdx.x;
    const int w    = tid >> 5;
    const int lane = tid & 31;
    const int grp  = lane >> 2;     // 0..7
    const int tg   = lane & 3;      // 0..3
    const int wm   = w & 1;
    const int wn   = w >> 1;

    const int lr  = tid >> 2;          // 0..63 (+64 on second pass)
    const int lc4 = (tid & 3) * 4;     // 0,4,8,12

    float acc[4][4][4];
    #pragma unroll
    for (int mt = 0; mt < 4; mt++)
        #pragma unroll
        for (int nt = 0; nt < 4; nt++)
            #pragma unroll
            for (int r = 0; r < 4; r++) acc[mt][nt][r] = 0.0f;

    auto issue = [&](int kt, int buf) {
        int kk = kt * GBK;
        #pragma unroll
        for (int i = 0; i < 2; i++) {
            int r = lr + i * 64;
            int gr = rowbase + r;
            if (gr >= NN) gr = NN - 1;   // clamp; garbage rows never stored
            cp16(&As[buf][r * SPAD + lc4], &A[gr * F_INN + kk + lc4]);
            cp16(&Bs[buf][r * SPAD + lc4], &Bsrc[r * F_INN + kk + lc4]);
        }
    };

    issue(0, 0);
    asm volatile("cp.async.commit_group;");

    // fused degree count: this block's 512-edge slice, overlapped with stage-0 DMA
    {
        int blin = blockIdx.y * 4 + blockIdx.x;     // 0..1563
        int e0 = blin * 512 + tid;
        if (e0 < EE) atomicAdd(&g_cnt[dstp[e0]], 1);
        if (e0 + 256 < EE) atomicAdd(&g_cnt[dstp[e0 + 256]], 1);
    }

    for (int kt = 0; kt < KT; kt++) {
        int buf = kt & 1;
        if (kt + 1 < KT) {
            issue(kt + 1, (kt + 1) & 1);
            asm volatile("cp.async.commit_group;");
            asm volatile("cp.async.wait_group 1;");
        } else {
            asm volatile("cp.async.wait_group 0;");
        }
        __syncthreads();

        #pragma unroll
        for (int ks = 0; ks < 2; ks++) {
            const int kof = ks * 8 + tg;
            unsigned af[4][4];
            #pragma unroll
            for (int mt = 0; mt < 4; mt++) {
                int r0 = wm * 64 + mt * 16 + grp;
                af[mt][0] = f2tf32(As[buf][r0 * SPAD + kof]);
                af[mt][1] = f2tf32(As[buf][(r0 + 8) * SPAD + kof]);
                af[mt][2] = f2tf32(As[buf][r0 * SPAD + kof + 4]);
                af[mt][3] = f2tf32(As[buf][(r0 + 8) * SPAD + kof + 4]);
            }
            unsigned bf[4][2];
            #pragma unroll
            for (int nt = 0; nt < 4; nt++) {
                int c0 = wn * 32 + nt * 8 + grp;
                bf[nt][0] = f2tf32(Bs[buf][c0 * SPAD + kof]);
                bf[nt][1] = f2tf32(Bs[buf][c0 * SPAD + kof + 4]);
            }
            #pragma unroll
            for (int mt = 0; mt < 4; mt++)
                #pragma unroll
                for (int nt = 0; nt < 4; nt++)
                    mma_tf32(acc[mt][nt][0], acc[mt][nt][1], acc[mt][nt][2], acc[mt][nt][3],
                             af[mt][0], af[mt][1], af[mt][2], af[mt][3],
                             bf[nt][0], bf[nt][1]);
        }
        __syncthreads();
    }

    // ---- store C ----
    #pragma unroll
    for (int mt = 0; mt < 4; mt++) {
        int row0 = rowbase + wm * 64 + mt * 16 + grp;
        int row1 = row0 + 8;
        #pragma unroll
        for (int nt = 0; nt < 4; nt++) {
            int col = ccol0 + wn * 32 + nt * 8 + 2 * tg;
            if (isfeat) {
                if (row0 < NN)
                    g_featb[row0 * 128 + (col >> 1)] =
                        __floats2bfloat162_rn(acc[mt][nt][0], acc[mt][nt][1]);
                if (row1 < NN)
                    g_featb[row1 * 128 + (col >> 1)] =
                        __floats2bfloat162_rn(acc[mt][nt][2], acc[mt][nt][3]);
            } else {
                if (row0 < NN)
                    *(float2*)&g_res[row0 * HD + col] = make_float2(acc[mt][nt][0], acc[mt][nt][1]);
                if (row1 < NN)
                    *(float2*)&g_res[row1 * HD + col] = make_float2(acc[mt][nt][2], acc[mt][nt][3]);
            }
        }
    }

    // ---- fused attention dots (feat blocks only) ----
    if (isfeat) {
        float al[4][2], ar[4][2];
        #pragma unroll
        for (int nt = 0; nt < 4; nt++) {
            int gc = colbase + wn * 32 + nt * 8 + 2 * tg;
            al[nt][0] = attn_l[gc]; al[nt][1] = attn_l[gc + 1];
            ar[nt][0] = attn_r[gc]; ar[nt][1] = attn_r[gc + 1];
        }
        #pragma unroll
        for (int mt = 0; mt < 4; mt++) {
            float pl0 = 0.f, pl1 = 0.f, pr0 = 0.f, pr1 = 0.f;
            #pragma unroll
            for (int nt = 0; nt < 4; nt++) {
                pl0 += acc[mt][nt][0] * al[nt][0] + acc[mt][nt][1] * al[nt][1];
                pl1 += acc[mt][nt][2] * al[nt][0] + acc[mt][nt][3] * al[nt][1];
                pr0 += acc[mt][nt][0] * ar[nt][0] + acc[mt][nt][1] * ar[nt][1];
                pr1 += acc[mt][nt][2] * ar[nt][0] + acc[mt][nt][3] * ar[nt][1];
            }
            #pragma unroll
            for (int o = 2; o; o >>= 1) {
                pl0 += __shfl_down_sync(0xffffffffu, pl0, o, 4);
                pl1 += __shfl_down_sync(0xffffffffu, pl1, o, 4);
                pr0 += __shfl_down_sync(0xffffffffu, pr0, o, 4);
                pr1 += __shfl_down_sync(0xffffffffu, pr1, o, 4);
            }
            if (tg == 0) {
                int hb = wn >> 1, wlo = wn & 1;
                int base = ((((wm * 2 + hb) * 2 + wlo) * 4 + mt) * 8 + grp) * 2;
                sdotL[base + 0] = pl0; sdotL[base + 1] = pl1;
                sdotR[base + 0] = pr0; sdotR[base + 1] = pr1;
            }
        }
        __syncthreads();
        int t = tid;
        int rhalf = t & 1, grp2 = (t >> 1) & 7, mt2 = (t >> 4) & 3;
        int hb2 = (t >> 6) & 1, wm2 = (t >> 7) & 1;
        int i0 = ((((wm2 * 2 + hb2) * 2 + 0) * 4 + mt2) * 8 + grp2) * 2 + rhalf;
        int i1 = ((((wm2 * 2 + hb2) * 2 + 1) * 4 + mt2) * 8 + grp2) * 2 + rhalf;
        int row = rowbase + wm2 * 64 + mt2 * 16 + rhalf * 8 + grp2;
        int headg = (colbase >> 6) + hb2;
        if (row < NN) {
            g_el[row * 4 + headg] = sdotL[i0] + sdotL[i1];
            g_er[row * 4 + headg] = sdotR[i0] + sdotR[i1];
        }
    }
}

// ---------------- K2: single-block scan of g_cnt -> g_off + V prep ----------
__global__ __launch_bounds__(1024) void k_scan1(const float* __restrict__ W_edge,
                                                const float* __restrict__ attn_e) {
    __shared__ int warps[32];
    int tid = threadIdx.x, lane = tid & 31, wid = tid >> 5;
    // V prep (threads 0-255); consumed by k_edge1 next launch
    if (tid < 256) {
        int j = tid & 63, h = tid >> 6;
        float s = 0.0f;
        #pragma unroll 8
        for (int d = 0; d < 64; d++)
            s += W_edge[(h * 64 + d) * 64 + j] * attn_e[h * 64 + d];
        g_V[j * 4 + h] = s;
    }
    int carry = 0;
    for (int base = 0; base < NN; base += 1024) {
        int idx = base + tid;
        int v = (idx < NN) ? g_cnt[idx] : 0;
        int x = v;
        #pragma unroll
        for (int o = 1; o < 32; o <<= 1) {
            int y = __shfl_up_sync(0xffffffffu, x, o);
            if (lane >= o) x += y;
        }
        if (lane == 31) warps[wid] = x;
        __syncthreads();
        if (wid == 0) {
            int wv = warps[lane];
            #pragma unroll
            for (int o = 1; o < 32; o <<= 1) {
                int y = __shfl_up_sync(0xffffffffu, wv, o);
                if (lane >= o) wv += y;
            }
            warps[lane] = wv;
        }
        __syncthreads();
        int pre = (wid > 0) ? warps[wid - 1] : 0;
        if (idx < NN) g_off[idx] = carry + pre + x - v;
        carry += warps[31];
        __syncthreads();
    }
}

// ---------------- K3: edge logits + CSR scatter, V in registers ----------
#define E_PER_WARP 64
#define E1_BLOCKS ((EE + 8 * E_PER_WARP - 1) / (8 * E_PER_WARP))   // 1563

__global__ __launch_bounds__(256) void k_edge1(const float* __restrict__ ef,
                                               const int* __restrict__ src,
                                               const int* __restrict__ dst) {
    int lane = threadIdx.x & 31;
    int warp = threadIdx.x >> 5;
    int sub = lane & 7, grp4 = lane >> 3;

    float4 vreg[8];
    #pragma unroll
    for (int j = 0; j < 8; j++)
        vreg[j] = *(const float4*)&g_V[(sub * 8 + j) * 4];

    int ebase = (blockIdx.x * 8 + warp) * E_PER_WARP + grp4;

    #pragma unroll 4
    for (int it = 0; it < E_PER_WARP / 4; it++) {
        int e = ebase + it * 4;
        bool valid = (e < EE);
        int ec = valid ? e : (EE - 1);          // clamp to keep warp converged

        const float4* p4 = (const float4*)&ef[(long)ec * 64 + sub * 8];
        float4 x0 = p4[0], x1 = p4[1];
        float xs[8] = {x0.x, x0.y, x0.z, x0.w, x1.x, x1.y, x1.z, x1.w};
        float a0 = 0.f, a1 = 0.f, a2 = 0.f, a3 = 0.f;
        #pragma unroll
        for (int j = 0; j < 8; j++) {
            a0 += xs[j] * vreg[j].x; a1 += xs[j] * vreg[j].y;
            a2 += xs[j] * vreg[j].z; a3 += xs[j] * vreg[j].w;
        }
        #pragma unroll
        for (int off = 4; off; off >>= 1) {
            a0 += __shfl_xor_sync(0xffffffffu, a0, off);
            a1 += __shfl_xor_sync(0xffffffffu, a1, off);
            a2 += __shfl_xor_sync(0xffffffffu, a2, off);
            a3 += __shfl_xor_sync(0xffffffffu, a3, off);
        }
        int s = src[ec], dd = dst[ec];
        int p = 0;
        if (sub == 0 && valid) p = g_off[dd] + atomicAdd(&g_cur[dd], 1);
        p = __shfl_sync(0xffffffffu, p, lane & ~7);
        if (valid) {
            if (sub == 0) g_esrc[p] = s;
            if (sub < 4) {
                int h = sub;
                float ee = (h == 0) ? a0 : (h == 1) ? a1 : (h == 2) ? a2 : a3;
                float v = g_el[s * 4 + h] + g_er[dd * 4 + h] + ee;
                v = (v > 0.0f) ? v : NEG_SLOPE * v;
                g_eex[p * 4 + h] = __expf(v);
            }
        }
    }
}

// ---------------- K4 (PROFILED): warp-per-node gather-reduce, direct ex LDG ---
__global__ __launch_bounds__(256) void k_agg(float* __restrict__ out) {
    int tid = threadIdx.x;
    int w = tid >> 5, lane = tid & 31;
    int n = blockIdx.x * 8 + w;
    if (n >= NN) return;
    int h = lane >> 3;                  // head of dims lane*8..lane*8+7
    int beg = g_off[n];
    int deg = g_cnt[n];

    float acc[8];
    #pragma unroll
    for (int r = 0; r < 8; r++) acc[r] = 0.0f;
    float sum_ex = 0.0f;                // per-head (h) partial

    for (int base = 0; base < deg; base += 32) {
        int chunk = min(32, deg - base);
        int srcs = (lane < chunk) ? g_esrc[beg + base + lane] : 0;
        #pragma unroll 4
        for (int i = 0; i < chunk; i++) {
            int s = __shfl_sync(0xffffffffu, srcs, i);
            float ex = g_eex[(beg + base + i) * 4 + h];   // broadcast-4 LDG
            uint4 v = *(const uint4*)&g_featb[s * 128 + lane * 4];
            float2 f0 = __bfloat1622float2(*(__nv_bfloat162*)&v.x);
            float2 f1 = __bfloat1622float2(*(__nv_bfloat162*)&v.y);
            float2 f2 = __bfloat1622float2(*(__nv_bfloat162*)&v.z);
            float2 f3 = __bfloat1622float2(*(__nv_bfloat162*)&v.w);
            acc[0] += ex * f0.x; acc[1] += ex * f0.y;
            acc[2] += ex * f1.x; acc[3] += ex * f1.y;
            acc[4] += ex * f2.x; acc[5] += ex * f2.y;
            acc[6] += ex * f3.x; acc[7] += ex * f3.y;
            sum_ex += ex;
        }
    }

    // restore zero-invariant for next run
    if (lane == 0) { g_cnt[n] = 0; g_cur[n] = 0; }

    float invd = 1.0f / fmaxf((float)deg, 1.0f);
    float inv_ex = (sum_ex > 0.0f) ? (1.0f / sum_ex) : 0.0f;
    float sc = inv_ex * invd;

    const float4* rs4 = (const float4*)&g_res[n * HD + lane * 8];
    float4 r0 = rs4[0], r1 = rs4[1];
    float4 o0 = make_float4(acc[0]*sc + r0.x, acc[1]*sc + r0.y,
                            acc[2]*sc + r0.z, acc[3]*sc + r0.w);
    float4 o1 = make_float4(acc[4]*sc + r1.x, acc[5]*sc + r1.y,
                            acc[6]*sc + r1.z, acc[7]*sc + r1.w);
    float4* op = (float4*)&out[n * HD + lane * 8];
    op[0] = o0; op[1] = o1;
}

// ---------------- launch ----------------
extern "C" void kernel_launch(void* const* d_in, const int* in_sizes, int n_in,
                              void* d_out, int out_size) {
    const float* h_in    = (const float*)d_in[0];
    const float* ef      = (const float*)d_in[1];
    const int*   src     = (const int*)d_in[2];
    const int*   dst     = (const int*)d_in[3];
    const float* W_fc    = (const float*)d_in[4];
    const float* W_edge  = (const float*)d_in[5];
    const float* W_res   = (const float*)d_in[6];
    const float* attn_l  = (const float*)d_in[7];
    const float* attn_r  = (const float*)d_in[8];
    const float* attn_e  = (const float*)d_in[9];
    float* out = (float*)d_out;

    dim3 ggrid(4, (NN + GBM - 1) / GBM);
    k_gemm_attn<<<ggrid, 256>>>(h_in, W_fc, W_res, attn_l, attn_r, dst); // 1

    k_scan1<<<1, 1024>>>(W_edge, attn_e);                                // 2

    k_edge1<<<E1_BLOCKS, 256>>>(ef, src, dst);                           // 3

    k_agg<<<(NN + 7) / 8, 256>>>(out);                                   // 4 (profiled)
}